// round 16
// baseline (speedup 1.0000x reference)
#include <cuda_runtime.h>
#include <cuda_fp16.h>
#include <math.h>
#include <stdint.h>

// ---------------- problem constants ----------------
namespace {
constexpr int Bc = 8, Sc = 512, Fc = 64, Dc = 512, Ic = 1024, NHc = 8, Lc = 2, Kc = 4;
constexpr int DHc = Ic / NHc;   // 128
constexpr int H1c = 32, OUTc = 24;
constexpr int TOK = Bc * Sc;    // 4096
// GEMM: 128x64 tile, BK=32, 3-stage; fp16 2-term (A single, W hi+lo)
constexpr int G_TILE_A = 128 * 32 * 2;   // 8 KB
constexpr int G_TILE_B = 64 * 32 * 2;    // 4 KB
constexpr int G_STG = G_TILE_A + 2 * G_TILE_B;   // 16 KB
constexpr int DSMG = 3 * G_STG + 1024;   // 50,176 B (3 CTAs/SM)
// mlstm v6 dynamic smem (float4 units)
constexpr int MSMEM = (1056 + 1056 + 1024 + 1024 + 256) * 16;   // 70,656 B
// gates v3 dynamic smem: 8 token rows x 3072 floats
constexpr int GSMEM = 8 * 3072 * 4;   // 98,304 B
// converted-weight buffer layout (elements)
constexpr long W_BASE  = 32768;             // in_w^T [512,64]
constexpr long W_UP    = 0;                 // per-layer offsets
constexpr long W_QK    = 1048576;           // q^T then k^T, [2048,1024]
constexpr long W_V     = 3145728;
constexpr long W_DN    = 4194304;
constexpr long W_LAYER = 4718592;
constexpr long W_TOTAL = W_BASE + 2 * W_LAYER;   // 9,469,952
constexpr int GWT_L = 2 * NHc * 3 * Ic;     // per-layer gate-weight^T floats (49152)
}

// ---------------- scratch (device globals; no allocations allowed) ----------------
__device__ float g_h   [TOK * Dc];
__device__ float g_up  [TOK * 2 * Ic];
__device__ float g_conv[TOK * Ic];
__device__ float g_qk  [TOK * 2 * Ic];    // q cols [0,1024), k cols [1024,2048)
__device__ float g_v   [TOK * Ic];
__device__ float g_ig  [Bc * NHc * Sc];
__device__ float g_fg  [Bc * NHc * Sc];
__device__ float g_cs  [Bc * NHc * Sc];
__device__ float g_gg  [Bc * NHc * Sc];   // g_t = ig_t - cs_t
__device__ float g_M   [Bc * NHc * Sc];   // prefix max of g
__device__ __align__(16) float g_gwt[Lc * GWT_L];   // transposed gate weights
__device__ __align__(16) __half g_ah [TOK * Ic];    // activation fp16 (generic A)
__device__ __align__(16) __half g_xmh[TOK * Ic];    // x_m fp16 (v-GEMM A)
__device__ __align__(16) __half g_whi[W_TOTAL];
__device__ __align__(16) __half g_wlo[W_TOTAL];

// ---------------- helpers ----------------
__device__ __forceinline__ float warpSum(float v) {
#pragma unroll
    for (int o = 16; o > 0; o >>= 1) v += __shfl_xor_sync(0xffffffffu, v, o);
    return v;
}
__device__ __forceinline__ float warpMax(float v) {
#pragma unroll
    for (int o = 16; o > 0; o >>= 1) v = fmaxf(v, __shfl_xor_sync(0xffffffffu, v, o));
    return v;
}
__device__ __forceinline__ uint32_t smem_u32(const void* p) {
    uint32_t a;
    asm("{ .reg .u64 t; cvta.to.shared.u64 t, %1; cvt.u32.u64 %0, t; }" : "=r"(a) : "l"(p));
    return a;
}
__device__ __forceinline__ void cp16(uint32_t saddr, const void* gaddr) {
    asm volatile("cp.async.cg.shared.global [%0], [%1], 16;" :: "r"(saddr), "l"(gaddr));
}
__device__ __forceinline__ void ldm_x4(uint32_t* r, uint32_t addr) {
    asm volatile("ldmatrix.sync.aligned.m8n8.x4.shared.b16 {%0,%1,%2,%3}, [%4];"
                 : "=r"(r[0]), "=r"(r[1]), "=r"(r[2]), "=r"(r[3]) : "r"(addr));
}
__device__ __forceinline__ void mma16816(float* d, const uint32_t* a, uint32_t b0, uint32_t b1) {
    asm volatile(
        "mma.sync.aligned.m16n8k16.row.col.f32.f16.f16.f32 "
        "{%0,%1,%2,%3}, {%4,%5,%6,%7}, {%8,%9}, {%0,%1,%2,%3};"
        : "+f"(d[0]), "+f"(d[1]), "+f"(d[2]), "+f"(d[3])
        : "r"(a[0]), "r"(a[1]), "r"(a[2]), "r"(a[3]), "r"(b0), "r"(b1));
}
__device__ __forceinline__ void wsplit(float w, __half& hi, __half& lo) {
    hi = __float2half(w);
    lo = __float2half(w - __half2float(hi));
}
__device__ __forceinline__ float siluf(float z) {
    return z / (1.f + __expf(-z));
}

// ---------------- one-shot prep: x->fp16 + weights->fp16 hi/lo + gate-w transpose ----
__global__ __launch_bounds__(1024)
void prep_kernel(const float* __restrict__ x, const float* __restrict__ in_w,
                 const float* __restrict__ up_w, const float* __restrict__ q_w,
                 const float* __restrict__ k_w, const float* __restrict__ v_w,
                 const float* __restrict__ down_w,
                 const float* __restrict__ ig_w, const float* __restrict__ fg_w,
                 __half* __restrict__ xh,
                 __half* __restrict__ whi, __half* __restrict__ wlo,
                 float* __restrict__ gwt) {
    int nb = blockIdx.x;
    int tx = threadIdx.x, ty = threadIdx.y;
    if (nb < 256) {
        int idx = nb * 1024 + ty * 32 + tx;
        xh[idx] = __float2half(x[idx]);
        return;
    }
    nb -= 256;
    if (nb >= 32 + 2 * 4608) {
        int nb2 = nb - (32 + 2 * 4608);
        int mat = nb2 / 24;
        int off = (nb2 % 24) * 1024 + ty * 32 + tx;   // 0..24575
        int l = mat >> 1, gate = mat & 1;
        const float* src = (gate ? fg_w : ig_w) + (long)l * 3 * Ic * NHc;
        float val = src[off];
        int i = off >> 3, hh = off & 7;
        gwt[(long)l * GWT_L + (gate * NHc + hh) * (3 * Ic) + i] = val;
        return;
    }
    const float* W; int K, N; long dst;
    if (nb < 32) { W = in_w; K = Fc; N = Dc; dst = 0; }
    else {
        nb -= 32;
        int l = nb / 4608, r = nb % 4608;
        long lb = W_BASE + (long)l * W_LAYER;
        if (r < 1024)      { W = up_w  + (long)l * Dc * 2 * Ic; K = Dc; N = 2 * Ic; dst = lb + W_UP; nb = r; }
        else if (r < 2048) { W = q_w   + (long)l * Ic * Ic;     K = Ic; N = Ic;     dst = lb + W_QK; nb = r - 1024; }
        else if (r < 3072) { W = k_w   + (long)l * Ic * Ic;     K = Ic; N = Ic;     dst = lb + W_QK + (long)Ic * Ic; nb = r - 2048; }
        else if (r < 4096) { W = v_w   + (long)l * Ic * Ic;     K = Ic; N = Ic;     dst = lb + W_V;  nb = r - 3072; }
        else               { W = down_w+ (long)l * Ic * Dc;     K = Ic; N = Dc;     dst = lb + W_DN; nb = r - 4096; }
    }
    int ntn = N / 32;
    int n0 = (nb % ntn) * 32, k0 = (nb / ntn) * 32;
    __shared__ float sh[32][33];
    sh[ty][tx] = W[(long)(k0 + ty) * N + n0 + tx];
    __syncthreads();
    float w = sh[tx][ty];                 // = W[k0+tx][n0+ty]
    long o = dst + (long)(n0 + ty) * K + k0 + tx;
    wsplit(w, whi[o], wlo[o]);
}

// ---------------- GEMM core (128x64, BK=32, 3-stage), fp16 2-term ----------------
template<bool ACC, bool BIAS, bool SPLIT>
__device__ __forceinline__
void gemm_body(const __half* __restrict__ A,
               const __half* __restrict__ Bhi, const __half* __restrict__ Blo,
               const float* __restrict__ bias, float* __restrict__ C, int N, int Kd,
               __half* __restrict__ Sh, int splitN,
               int bm, int bn, char* sm) {
    uint32_t sbase = smem_u32(sm);
    int tid = threadIdx.x, wid = tid >> 5, lane = tid & 31;
    int m0 = (wid >> 1) * 32, n0 = (wid & 1) * 32;

    float acc[2][4][4];
#pragma unroll
    for (int i = 0; i < 2; i++)
#pragma unroll
        for (int j = 0; j < 4; j++)
#pragma unroll
            for (int t = 0; t < 4; t++) acc[i][j][t] = 0.f;

    const int nchunk = Kd >> 5;

    auto load_chunk = [&](int stage, int k0) {
        uint32_t sA = sbase + stage * G_STG;
#pragma unroll
        for (int u2 = 0; u2 < 2; u2++) {
            int u = u2 * 256 + tid;             // 0..511: A 128 rows x 4 chunks
            int row = u >> 2;
            uint32_t off = (uint32_t)u << 4;
            uint32_t sw = off ^ ((off >> 3) & 0x30);
            long ga = (long)(bm + row) * Kd + k0 + ((u & 3) << 3);
            cp16(sA + sw, A + ga);
        }
        {
            int u = tid;                        // B: 64 rows x 4 chunks = 256
            int row = u >> 2;
            uint32_t off = (uint32_t)u << 4;
            uint32_t sw = off ^ ((off >> 3) & 0x30);
            long gb = (long)(bn + row) * Kd + k0 + ((u & 3) << 3);
            cp16(sA + G_TILE_A + sw,            Bhi + gb);
            cp16(sA + G_TILE_A + G_TILE_B + sw, Blo + gb);
        }
        asm volatile("cp.async.commit_group;" ::: "memory");
    };

    // precomputed LDSM offsets (k16=0); k16=1 = XOR 32
    int rsel = lane & 15;
    uint32_t csel = ((uint32_t)(lane >> 4) & 1) << 4;
    uint32_t offA[2], offB[2];
#pragma unroll
    for (int i = 0; i < 2; i++) {
        uint32_t r = (uint32_t)(m0 + i * 16 + rsel);
        offA[i] = r * 64 + (csel ^ ((r * 8) & 0x30));
    }
#pragma unroll
    for (int p = 0; p < 2; p++) {
        uint32_t r = (uint32_t)(n0 + p * 16 + rsel);
        offB[p] = r * 64 + (csel ^ ((r * 8) & 0x30));
    }

    load_chunk(0, 0);
    if (nchunk > 1) load_chunk(1, 32);
    else asm volatile("cp.async.commit_group;" ::: "memory");

    for (int c = 0; c < nchunk; c++) {
        asm volatile("cp.async.wait_group 1;" ::: "memory");
        __syncthreads();
        if (c + 2 < nchunk) load_chunk((c + 2) % 3, (c + 2) << 5);
        else asm volatile("cp.async.commit_group;" ::: "memory");

        uint32_t base = sbase + (c % 3) * G_STG;
#pragma unroll
        for (int k16 = 0; k16 < 2; k16++) {
            uint32_t x = (uint32_t)k16 * 32;
            uint32_t ah[2][4], bh[2][4], bl[2][4];
#pragma unroll
            for (int i = 0; i < 2; i++) ldm_x4(ah[i], base + (offA[i] ^ x));
#pragma unroll
            for (int p = 0; p < 2; p++) {
                ldm_x4(bh[p], base + G_TILE_A + (offB[p] ^ x));
                ldm_x4(bl[p], base + G_TILE_A + G_TILE_B + (offB[p] ^ x));
            }
            // term-major: T1 = A*Whi, T2 = A*Wlo
#pragma unroll
            for (int i = 0; i < 2; i++)
#pragma unroll
                for (int p = 0; p < 2; p++)
#pragma unroll
                    for (int q = 0; q < 2; q++)
                        mma16816(acc[i][p * 2 + q], ah[i], bh[p][q], bh[p][q + 2]);
#pragma unroll
            for (int i = 0; i < 2; i++)
#pragma unroll
                for (int p = 0; p < 2; p++)
#pragma unroll
                    for (int q = 0; q < 2; q++)
                        mma16816(acc[i][p * 2 + q], ah[i], bl[p][q], bl[p][q + 2]);
        }
    }

    int gid = lane >> 2, tig = lane & 3;
#pragma unroll
    for (int i = 0; i < 2; i++) {
        int row0 = bm + m0 + i * 16 + gid;
#pragma unroll
        for (int j = 0; j < 4; j++) {
            int col = bn + n0 + j * 8 + tig * 2;
            float o0 = acc[i][j][0], o1 = acc[i][j][1];
            float o2 = acc[i][j][2], o3 = acc[i][j][3];
            if (BIAS) {
                float b0 = bias[col], b1 = bias[col + 1];
                o0 += b0; o1 += b1; o2 += b0; o3 += b1;
            }
            float* p0 = C + (long)row0 * N + col;
            float* p1 = C + (long)(row0 + 8) * N + col;
            if (ACC) {
                float2 c0 = *(float2*)p0, c1 = *(float2*)p1;
                o0 += c0.x; o1 += c0.y; o2 += c1.x; o3 += c1.y;
            }
            *(float2*)p0 = make_float2(o0, o1);
            *(float2*)p1 = make_float2(o2, o3);
            if (SPLIT && col < splitN) {
                *(__half2*)(Sh + (long)row0 * splitN + col) =
                    __floats2half2_rn(o0, o1);
                *(__half2*)(Sh + (long)(row0 + 8) * splitN + col) =
                    __floats2half2_rn(o2, o3);
            }
        }
    }
}

template<bool ACC, bool BIAS, bool SPLIT>
__global__ __launch_bounds__(256, 3)
void mma_gemm(const __half* __restrict__ A,
              const __half* __restrict__ Bhi, const __half* __restrict__ Blo,
              const float* __restrict__ bias, float* __restrict__ C, int N, int Kd,
              __half* __restrict__ Sh, int splitN) {
    extern __shared__ char dsm[];
    char* sm = (char*)(((uintptr_t)dsm + 1023) & ~(uintptr_t)1023);
    gemm_body<ACC, BIAS, SPLIT>(A, Bhi, Blo, bias, C, N, Kd, Sh, splitN,
                                blockIdx.y * 128, blockIdx.x * 64, sm);
}

// merged dual-operand GEMM: blockIdx.x < nx1 -> op1, else op2 (same M, same Kd)
__global__ __launch_bounds__(256, 3)
void mma_gemm2(const __half* __restrict__ A1,
               const __half* __restrict__ B1h, const __half* __restrict__ B1l,
               float* __restrict__ C1, int N1, int nx1,
               const __half* __restrict__ A2,
               const __half* __restrict__ B2h, const __half* __restrict__ B2l,
               float* __restrict__ C2, int N2, int Kd) {
    extern __shared__ char dsm[];
    char* sm = (char*)(((uintptr_t)dsm + 1023) & ~(uintptr_t)1023);
    int bx = blockIdx.x;
    if (bx < nx1) {
        gemm_body<false, false, false>(A1, B1h, B1l, nullptr, C1, N1, Kd,
                                       nullptr, 0, blockIdx.y * 128, bx * 64, sm);
    } else {
        gemm_body<false, false, false>(A2, B2h, B2l, nullptr, C2, N2, Kd,
                                       nullptr, 0, blockIdx.y * 128, (bx - nx1) * 64, sm);
    }
}

// ---------------- LayerNorm over D=512 -> fp16 directly ----------------
__global__ __launch_bounds__(256)
void layernorm_kernel(const float* __restrict__ in, const float* __restrict__ w,
                      const float* __restrict__ b, __half* __restrict__ oh) {
    int row = blockIdx.x;
    const float* x = in + row * Dc;
    int tid = threadIdx.x;
    float v0 = x[tid], v1 = x[tid + 256];
    float s = v0 + v1, sq = v0 * v0 + v1 * v1;
    s = warpSum(s); sq = warpSum(sq);
    __shared__ float sS[8], sQ[8];
    int w8 = tid >> 5, lane = tid & 31;
    if (lane == 0) { sS[w8] = s; sQ[w8] = sq; }
    __syncthreads();
    float Sv = 0.f, Qv = 0.f;
#pragma unroll
    for (int i = 0; i < 8; i++) { Sv += sS[i]; Qv += sQ[i]; }
    float mu = Sv * (1.f / Dc);
    float var = Qv * (1.f / Dc) - mu * mu;
    float r = rsqrtf(var + 1e-5f);
    float y0 = (v0 - mu) * r * w[tid]       + b[tid];
    float y1 = (v1 - mu) * r * w[tid + 256] + b[tid + 256];
    oh[row * Dc + tid]       = __float2half(y0);
    oh[row * Dc + tid + 256] = __float2half(y1);
}

// ---------------- causal conv (K=4) + SiLU -> fp32 + fp16 ----------------
__global__ __launch_bounds__(256)
void conv_silu_kernel(const float* __restrict__ up, const float* __restrict__ cw,
                      const float* __restrict__ cb, float* __restrict__ out,
                      __half* __restrict__ oh) {
    int idx = blockIdx.x * 256 + threadIdx.x;   // over TOK*I
    int i = idx & (Ic - 1);
    int bs = idx >> 10;
    int s = bs & (Sc - 1);
    float acc = cb[i];
#pragma unroll
    for (int j = 0; j < Kc; j++) {
        int sp = s - (Kc - 1) + j;
        if (sp >= 0) acc += up[(bs - (Kc - 1) + j) * (2 * Ic) + i] * cw[i * Kc + j];
    }
    float sg = 1.f / (1.f + __expf(-acc));
    float o = acc * sg;
    out[idx] = o;
    oh[idx] = __float2half(o);
}

// ---------------- gates v3: 8 tokens per block, weight reuse x8 ----------------
__global__ __launch_bounds__(512)
void gates_kernel(const float* __restrict__ qk, const float* __restrict__ v,
                  const float* __restrict__ gwt,
                  const float* __restrict__ igb, const float* __restrict__ fgb,
                  float* __restrict__ ig, float* __restrict__ fg) {
    extern __shared__ float rows[];            // [8][3072]
    int bs0 = blockIdx.x * 8;
    for (int u = threadIdx.x; u < 8 * 3 * Ic; u += 512) {
        int gg2 = u / (3 * Ic);
        int i = u - gg2 * 3 * Ic;
        long bs = bs0 + gg2;
        float val;
        if (i < Ic)           val = qk[bs * 2048 + i];
        else if (i < 2 * Ic)  val = qk[bs * 2048 + 1024 + (i - Ic)];
        else                  val = v[bs * Ic + (i - 2 * Ic)];
        rows[gg2 * 3 * Ic + i] = val;
    }
    __syncthreads();
    int w = threadIdx.x >> 5, lane = threadIdx.x & 31;
    int h = w & 7, gate = w >> 3;
    const float* W = gwt + (gate * NHc + h) * (3 * Ic);
    float sum[8] = {0.f, 0.f, 0.f, 0.f, 0.f, 0.f, 0.f, 0.f};
    for (int i = lane * 4; i < 3 * Ic; i += 128) {
        float4 wv = *(const float4*)(W + i);
#pragma unroll
        for (int gg2 = 0; gg2 < 8; gg2++) {
            float4 rv = *(const float4*)(rows + gg2 * 3 * Ic + i);
            sum[gg2] += rv.x * wv.x + rv.y * wv.y + rv.z * wv.z + rv.w * wv.w;
        }
    }
#pragma unroll
    for (int gg2 = 0; gg2 < 8; gg2++) sum[gg2] = warpSum(sum[gg2]);
    if (lane == 0) {
#pragma unroll
        for (int gg2 = 0; gg2 < 8; gg2++) {
            int bs = bs0 + gg2;
            int b = bs >> 9, s = bs & (Sc - 1);
            int idx = (b * NHc + h) * Sc + s;
            if (gate == 0) ig[idx] = sum[gg2] + igb[h];
            else           fg[idx] = sum[gg2] + fgb[h];
        }
    }
}

// ---------------- scan: cs = cumsum(logsigmoid(fg)); g = ig - cs; M = prefixmax(g) --
__global__ __launch_bounds__(32)
void scan_kernel(const float* __restrict__ fg, const float* __restrict__ ig,
                 float* __restrict__ cs, float* __restrict__ g, float* __restrict__ M) {
    int bh = blockIdx.x, lane = threadIdx.x;
    const float* fp = fg + bh * Sc;
    const float* ip = ig + bh * Sc;
    int base = lane * 16;

    float lcs[16];
    float run = 0.f;
#pragma unroll
    for (int i = 0; i < 16; i++) {
        float f = fp[base + i];
        float ls = fminf(f, 0.f) - log1pf(__expf(-fabsf(f)));
        run += ls;
        lcs[i] = run;
    }
    float v = run;
#pragma unroll
    for (int o = 1; o < 32; o <<= 1) {
        float u = __shfl_up_sync(0xffffffffu, v, o);
        if (lane >= o) v += u;
    }
    float ex = v - run;

    float gv[16], pm[16];
    float rm = -1e30f;
#pragma unroll
    for (int i = 0; i < 16; i++) {
        lcs[i] += ex;
        gv[i] = ip[base + i] - lcs[i];
        rm = fmaxf(rm, gv[i]);
        pm[i] = rm;
    }
    float w = rm;
#pragma unroll
    for (int o = 1; o < 32; o <<= 1) {
        float u = __shfl_up_sync(0xffffffffu, w, o);
        if (lane >= o) w = fmaxf(w, u);
    }
    float exm = __shfl_up_sync(0xffffffffu, w, 1);
    if (lane == 0) exm = -1e30f;

#pragma unroll
    for (int i = 0; i < 16; i++) {
        cs[bh * Sc + base + i] = lcs[i];
        g [bh * Sc + base + i] = gv[i];
        M [bh * Sc + base + i] = fmaxf(exm, pm[i]);
    }
}

// ---------------- mLSTM v6: triangle-paired + FUSED groupnorm/skip/z-gate epilogue --
// grid (B*NH, 8); emits hs in fp16 directly (down-GEMM A operand).
__global__ __launch_bounds__(256)
void mlstm_kernel(const float* __restrict__ qk, const float* __restrict__ v,
                  const float* __restrict__ g, const float* __restrict__ M,
                  const float* __restrict__ cs,
                  const float* __restrict__ gnw, const float* __restrict__ skw,
                  const float* __restrict__ conv, const float* __restrict__ up,
                  __half* __restrict__ oh) {
    extern __shared__ float4 dyn4[];
    float4* ks4 = dyn4;                       // [tt*33 + c4]   (1056)
    float4* vs4 = dyn4 + 1056;                // [tt*33 + c4]   (1056)
    float4* qA  = dyn4 + 2112;                // [warp*128 + r*32 + d4] (1024)
    float4* qB  = dyn4 + 3136;                // (1024)
    float4* cst = dyn4 + 4160;                // [warp*32 + lane] (256)

    int bh = blockIdx.x;
    int b = bh >> 3, h = bh & 7;
    int warp = threadIdx.x >> 5, lane = threadIdx.x & 31;
    int y1 = blockIdx.y, y2 = 15 - y1;
    int s0A = y1 * 32 + warp * 4;
    int s0B = y2 * 32 + warp * 4;

    const float sc = 0.08838834764831845f;   // 1/sqrt(128)
    float MsA[4], csA[4], MsB[4], csB[4];
#pragma unroll
    for (int r = 0; r < 4; r++) {
        int sa = s0A + r, sb = s0B + r;
        float4 qa = *(const float4*)(qk + (long)(b * Sc + sa) * 2048 + h * DHc + lane * 4);
        qa.x *= sc; qa.y *= sc; qa.z *= sc; qa.w *= sc;
        qA[warp * 128 + r * 32 + lane] = qa;
        float4 qb = *(const float4*)(qk + (long)(b * Sc + sb) * 2048 + h * DHc + lane * 4);
        qb.x *= sc; qb.y *= sc; qb.z *= sc; qb.w *= sc;
        qB[warp * 128 + r * 32 + lane] = qb;
        MsA[r] = M[bh * Sc + sa]; csA[r] = cs[bh * Sc + sa];
        MsB[r] = M[bh * Sc + sb]; csB[r] = cs[bh * Sc + sb];
    }
    __syncwarp();

    const float* gg = g + bh * Sc;
    float oA[4][4], oB[4][4];
#pragma unroll
    for (int r = 0; r < 4; r++)
#pragma unroll
        for (int j = 0; j < 4; j++) { oA[r][j] = 0.f; oB[r][j] = 0.f; }
    float accA[4] = {0.f, 0.f, 0.f, 0.f};
    float accB[4] = {0.f, 0.f, 0.f, 0.f};

    int ntile = y2 + 1;
    for (int tt0 = 0; tt0 < ntile; tt0++) {
        int t0 = tt0 * 32;
        __syncthreads();
        for (int idx = threadIdx.x; idx < 32 * 32; idx += 256) {
            int tt = idx >> 5, c4 = idx & 31;
            long tr = (long)(b * Sc + t0 + tt);
            ks4[tt * 33 + c4] = *(const float4*)(qk + tr * 2048 + 1024 + h * DHc + c4 * 4);
            vs4[tt * 33 + c4] = *(const float4*)(v + tr * 1024 + h * DHc + c4 * 4);
        }
        __syncthreads();

        bool actA = (tt0 <= y1);
        int t = t0 + lane;
        float gv = gg[t];

        float T0B = warpMax((t <= s0B + 3) ? gv : -1e30f);
        float wtB = (t <= s0B + 3) ? __expf(gv - T0B) : 0.f;
        float T0A = 0.f, wtA = 0.f;
        if (actA) {
            T0A = warpMax((t <= s0A + 3) ? gv : -1e30f);
            wtA = (t <= s0A + 3) ? __expf(gv - T0A) : 0.f;
        }

        float dA[4] = {0.f, 0.f, 0.f, 0.f};
        float dB[4] = {0.f, 0.f, 0.f, 0.f};
        if (actA) {
#pragma unroll
            for (int d4 = 0; d4 < 32; d4++) {
                float4 k4 = ks4[lane * 33 + d4];
#pragma unroll
                for (int r = 0; r < 4; r++) {
                    float4 qa = qA[warp * 128 + r * 32 + d4];
                    dA[r] += qa.x * k4.x + qa.y * k4.y + qa.z * k4.z + qa.w * k4.w;
                    float4 qb = qB[warp * 128 + r * 32 + d4];
                    dB[r] += qb.x * k4.x + qb.y * k4.y + qb.z * k4.z + qb.w * k4.w;
                }
            }
        } else {
#pragma unroll
            for (int d4 = 0; d4 < 32; d4++) {
                float4 k4 = ks4[lane * 33 + d4];
#pragma unroll
                for (int r = 0; r < 4; r++) {
                    float4 qb = qB[warp * 128 + r * 32 + d4];
                    dB[r] += qb.x * k4.x + qb.y * k4.y + qb.z * k4.z + qb.w * k4.w;
                }
            }
        }

        if (actA) {
            float cA[4];
#pragma unroll
            for (int r = 0; r < 4; r++) {
                float wf = wtA * __expf(T0A - MsA[r]);
                cA[r] = (t <= s0A + r) ? dA[r] * wf : 0.f;
                accA[r] += cA[r];
            }
            cst[warp * 32 + lane] = make_float4(cA[0], cA[1], cA[2], cA[3]);
            __syncwarp();
#pragma unroll
            for (int tt = 0; tt < 32; tt++) {
                float4 c4v = cst[warp * 32 + tt];
                float4 v4 = vs4[tt * 33 + lane];
                oA[0][0] += c4v.x * v4.x; oA[0][1] += c4v.x * v4.y; oA[0][2] += c4v.x * v4.z; oA[0][3] += c4v.x * v4.w;
                oA[1][0] += c4v.y * v4.x; oA[1][1] += c4v.y * v4.y; oA[1][2] += c4v.y * v4.z; oA[1][3] += c4v.y * v4.w;
                oA[2][0] += c4v.z * v4.x; oA[2][1] += c4v.z * v4.y; oA[2][2] += c4v.z * v4.z; oA[2][3] += c4v.z * v4.w;
                oA[3][0] += c4v.w * v4.x; oA[3][1] += c4v.w * v4.y; oA[3][2] += c4v.w * v4.z; oA[3][3] += c4v.w * v4.w;
            }
            __syncwarp();
        }
        {
            float cB[4];
#pragma unroll
            for (int r = 0; r < 4; r++) {
                float wf = wtB * __expf(T0B - MsB[r]);
                cB[r] = (t <= s0B + r) ? dB[r] * wf : 0.f;
                accB[r] += cB[r];
            }
            cst[warp * 32 + lane] = make_float4(cB[0], cB[1], cB[2], cB[3]);
            __syncwarp();
#pragma unroll
            for (int tt = 0; tt < 32; tt++) {
                float4 c4v = cst[warp * 32 + tt];
                float4 v4 = vs4[tt * 33 + lane];
                oB[0][0] += c4v.x * v4.x; oB[0][1] += c4v.x * v4.y; oB[0][2] += c4v.x * v4.z; oB[0][3] += c4v.x * v4.w;
                oB[1][0] += c4v.y * v4.x; oB[1][1] += c4v.y * v4.y; oB[1][2] += c4v.y * v4.z; oB[1][3] += c4v.y * v4.w;
                oB[2][0] += c4v.z * v4.x; oB[2][1] += c4v.z * v4.y; oB[2][2] += c4v.z * v4.z; oB[2][3] += c4v.z * v4.w;
                oB[3][0] += c4v.w * v4.x; oB[3][1] += c4v.w * v4.y; oB[3][2] += c4v.w * v4.z; oB[3][3] += c4v.w * v4.w;
            }
            __syncwarp();
        }
    }

    // ---- fused epilogue: normalize + groupnorm + skip + z-gate -> fp16 hs ----
    float4 gw = *(const float4*)(gnw + h * DHc + lane * 4);
    float4 sw = *(const float4*)(skw + h * DHc + lane * 4);
#pragma unroll
    for (int side = 0; side < 2; side++) {
        float* accS  = side ? accB : accA;
        float (*oS)[4] = side ? oB : oA;
        float* MsS   = side ? MsB : MsA;
        float* csS   = side ? csB : csA;
        int s0 = side ? s0B : s0A;
#pragma unroll
        for (int r = 0; r < 4; r++) {
            float a = warpSum(accS[r]);
            float nrm = fmaxf(fabsf(a), __expf(-(csS[r] + MsS[r])));
            float inv = 1.f / (nrm + 1e-6f);
            float x0 = oS[r][0] * inv, x1 = oS[r][1] * inv;
            float x2 = oS[r][2] * inv, x3 = oS[r][3] * inv;
            float sm1 = warpSum(x0 + x1 + x2 + x3);
            float sm2 = warpSum(x0 * x0 + x1 * x1 + x2 * x2 + x3 * x3);
            float mu = sm1 * (1.f / DHc);
            float var = sm2 * (1.f / DHc) - mu * mu;
            float rr = rsqrtf(var + 1e-5f);
            long bs = (long)(b * Sc + s0 + r);
            long ci = bs * Ic + h * DHc + lane * 4;
            float4 cv = *(const float4*)(conv + ci);
            float4 z4 = *(const float4*)(up + bs * 2048 + 1024 + h * DHc + lane * 4);
            float r0 = ((x0 - mu) * rr * gw.x + sw.x * cv.x) * siluf(z4.x);
            float r1 = ((x1 - mu) * rr * gw.y + sw.y * cv.y) * siluf(z4.y);
            float r2 = ((x2 - mu) * rr * gw.z + sw.z * cv.z) * siluf(z4.z);
            float r3 = ((x3 - mu) * rr * gw.w + sw.w * cv.w) * siluf(z4.w);
            __half2* dst = (__half2*)(oh + ci);
            dst[0] = __floats2half2_rn(r0, r1);
            dst[1] = __floats2half2_rn(r2, r3);
        }
    }
}

// ---------------- tail ----------------
__global__ __launch_bounds__(256)
void final_kernel(const float* __restrict__ h, const float* __restrict__ pw,
                  const float* __restrict__ pb, const float* __restrict__ w1,
                  const float* __restrict__ b1, const float* __restrict__ w2,
                  const float* __restrict__ b2, float* __restrict__ out) {
    int b = blockIdx.x;
    __shared__ float ln[Dc];
    __shared__ float hid[H1c];
    __shared__ float sS[8], sQ[8];
    const float* x = h + (b * Sc + Sc - 1) * Dc;
    int tid = threadIdx.x;
    float v0 = x[tid], v1 = x[tid + 256];
    float s = v0 + v1, sq = v0 * v0 + v1 * v1;
    s = warpSum(s); sq = warpSum(sq);
    int w = tid >> 5, lane = tid & 31;
    if (lane == 0) { sS[w] = s; sQ[w] = sq; }
    __syncthreads();
    float Sv = 0.f, Qv = 0.f;
#pragma unroll
    for (int i = 0; i < 8; i++) { Sv += sS[i]; Qv += sQ[i]; }
    float mu = Sv * (1.f / Dc);
    float var = Qv * (1.f / Dc) - mu * mu;
    float r = rsqrtf(var + 1e-5f);
    ln[tid]       = (v0 - mu) * r * pw[tid]       + pb[tid];
    ln[tid + 256] = (v1 - mu) * r * pw[tid + 256] + pb[tid + 256];
    __syncthreads();
#pragma unroll
    for (int jj = 0; jj < 4; jj++) {
        int o = w + 8 * jj;
        float sum = 0.f;
        for (int d = lane; d < Dc; d += 32) sum += ln[d] * w1[d * H1c + o];
        sum = warpSum(sum);
        if (lane == 0) hid[o] = fmaxf(sum + b1[o], 0.f);
    }
    __syncthreads();
    if (tid < OUTc) {
        float s2 = b2[tid];
#pragma unroll
        for (int j = 0; j < H1c; j++) s2 += hid[j] * w2[j * OUTc + tid];
        out[b * OUTc + tid] = s2;
    }
}

// ---------------- launch ----------------
extern "C" void kernel_launch(void* const* d_in, const int* in_sizes, int n_in,
                              void* d_out, int out_size) {
    const float* x     = (const float*)d_in[0];
    const float* in_w  = (const float*)d_in[1];
    const float* in_b  = (const float*)d_in[2];
    const float* ln_w  = (const float*)d_in[3];
    const float* ln_b  = (const float*)d_in[4];
    const float* up_w  = (const float*)d_in[5];
    const float* conv_w= (const float*)d_in[6];
    const float* conv_b= (const float*)d_in[7];
    const float* q_w   = (const float*)d_in[8];
    const float* k_w   = (const float*)d_in[9];
    const float* v_w   = (const float*)d_in[10];
    const float* ig_w  = (const float*)d_in[11];
    const float* ig_b  = (const float*)d_in[12];
    const float* fg_w  = (const float*)d_in[13];
    const float* fg_b  = (const float*)d_in[14];
    const float* gn_w  = (const float*)d_in[15];
    const float* skip_w= (const float*)d_in[16];
    const float* down_w= (const float*)d_in[17];
    const float* post_w= (const float*)d_in[18];
    const float* post_b= (const float*)d_in[19];
    const float* h1_w  = (const float*)d_in[20];
    const float* h1_b  = (const float*)d_in[21];
    const float* h2_w  = (const float*)d_in[22];
    const float* h2_b  = (const float*)d_in[23];

    float *h, *up, *conv, *qkb, *v, *ig, *fg, *cs, *gg, *Mg, *gwt;
    __half *ah, *xmh, *whi, *wlo;
    cudaGetSymbolAddress((void**)&h,    g_h);
    cudaGetSymbolAddress((void**)&up,   g_up);
    cudaGetSymbolAddress((void**)&conv, g_conv);
    cudaGetSymbolAddress((void**)&qkb,  g_qk);
    cudaGetSymbolAddress((void**)&v,    g_v);
    cudaGetSymbolAddress((void**)&ig,   g_ig);
    cudaGetSymbolAddress((void**)&fg,   g_fg);
    cudaGetSymbolAddress((void**)&cs,   g_cs);
    cudaGetSymbolAddress((void**)&gg,   g_gg);
    cudaGetSymbolAddress((void**)&Mg,   g_M);
    cudaGetSymbolAddress((void**)&gwt,  g_gwt);
    cudaGetSymbolAddress((void**)&ah,   g_ah);
    cudaGetSymbolAddress((void**)&xmh,  g_xmh);
    cudaGetSymbolAddress((void**)&whi,  g_whi);
    cudaGetSymbolAddress((void**)&wlo,  g_wlo);

    cudaFuncSetAttribute(mma_gemm<false, false, false>, cudaFuncAttributeMaxDynamicSharedMemorySize, DSMG);
    cudaFuncSetAttribute(mma_gemm<false, false, true >, cudaFuncAttributeMaxDynamicSharedMemorySize, DSMG);
    cudaFuncSetAttribute(mma_gemm<false, true,  false>, cudaFuncAttributeMaxDynamicSharedMemorySize, DSMG);
    cudaFuncSetAttribute(mma_gemm<true,  false, false>, cudaFuncAttributeMaxDynamicSharedMemorySize, DSMG);
    cudaFuncSetAttribute(mma_gemm2, cudaFuncAttributeMaxDynamicSharedMemorySize, DSMG);
    cudaFuncSetAttribute(mlstm_kernel, cudaFuncAttributeMaxDynamicSharedMemorySize, MSMEM);
    cudaFuncSetAttribute(gates_kernel, cudaFuncAttributeMaxDynamicSharedMemorySize, GSMEM);

    // launch 0: all weight conversion + x convert + gate-w transpose (one kernel)
    prep_kernel<<<256 + 32 + 2 * 4608 + 96, dim3(32, 32)>>>(
        x, in_w, up_w, q_w, k_w, v_w, down_w, ig_w, fg_w, ah, whi, wlo, gwt);
    // launch 1: h = x @ in_w + in_b
    mma_gemm<false, true, false><<<dim3(Dc / 64, TOK / 128), 256, DSMG>>>(
        ah, whi, wlo, in_b, h, Dc, Fc, nullptr, 0);

    for (int l = 0; l < Lc; l++) {
        long lb = W_BASE + (long)l * W_LAYER;
        layernorm_kernel<<<TOK, 256>>>(h, ln_w + l * Dc, ln_b + l * Dc, ah);
        // up = xn @ up_w[l]  (+ x_m fp16 for v-GEMM)   << PROFILED SLOT >>
        mma_gemm<false, false, true><<<dim3(2 * Ic / 64, TOK / 128), 256, DSMG>>>(
            ah, whi + lb + W_UP, wlo + lb + W_UP, nullptr, up, 2 * Ic, Dc, xmh, Ic);
        // conv_act = silu(causal_conv(x_m))  (+ its own fp16)
        conv_silu_kernel<<<TOK * Ic / 256, 256>>>(up, conv_w + l * Ic * Kc, conv_b + l * Ic,
                                                  conv, ah);
        // merged launch: qk = conv @ [q|k]  AND  v = x_m @ v_w  (K=1024 both)
        mma_gemm2<<<dim3(2 * Ic / 64 + Ic / 64, TOK / 128), 256, DSMG>>>(
            ah, whi + lb + W_QK, wlo + lb + W_QK, qkb, 2 * Ic, 2 * Ic / 64,
            xmh, whi + lb + W_V, wlo + lb + W_V, v, Ic, Ic);
        // gates (8-token blocked) + scan
        gates_kernel<<<TOK / 8, 512, GSMEM>>>(qkb, v, gwt + (long)l * GWT_L,
                                              ig_b + l * NHc, fg_b + l * NHc, ig, fg);
        scan_kernel<<<Bc * NHc, 32>>>(fg, ig, cs, gg, Mg);
        // attention + fused groupnorm/skip/z-gate -> hs fp16 (down-GEMM A)
        mlstm_kernel<<<dim3(Bc * NHc, 8), 256, MSMEM>>>(
            qkb, v, gg, Mg, cs, gn_w + l * Ic, skip_w + l * Ic, conv, up, ah);
        // h += hs @ down_w[l]
        mma_gemm<true, false, false><<<dim3(Dc / 64, TOK / 128), 256, DSMG>>>(
            ah, whi + lb + W_DN, wlo + lb + W_DN, nullptr, h, Dc, Ic, nullptr, 0);
    }

    final_kernel<<<Bc, 256>>>(h, post_w, post_b, h1_w, h1_b, h2_w, h2_b, (float*)d_out);
}

// round 17
// speedup vs baseline: 1.0180x; 1.0180x over previous
#include <cuda_runtime.h>
#include <cuda_fp16.h>
#include <math.h>
#include <stdint.h>

// ---------------- problem constants ----------------
namespace {
constexpr int Bc = 8, Sc = 512, Fc = 64, Dc = 512, Ic = 1024, NHc = 8, Lc = 2, Kc = 4;
constexpr int DHc = Ic / NHc;   // 128
constexpr int H1c = 32, OUTc = 24;
constexpr int TOK = Bc * Sc;    // 4096
// GEMM: 128x64 tile, BK=32, 3-stage; fp16 2-term (A single, W hi+lo)
constexpr int G_TILE_A = 128 * 32 * 2;   // 8 KB
constexpr int G_TILE_B = 64 * 32 * 2;    // 4 KB
constexpr int G_STG = G_TILE_A + 2 * G_TILE_B;   // 16 KB
constexpr int DSMG = 3 * G_STG + 1024;   // 50,176 B (3 CTAs/SM)
// mlstm v6 dynamic smem (float4 units)
constexpr int MSMEM = (1056 + 1056 + 1024 + 1024 + 256) * 16;   // 70,656 B
// gates v2 dynamic smem: 4 token rows x 3072 floats (4 CTAs/SM)
constexpr int GSMEM = 4 * 3072 * 4;   // 49,152 B
// converted-weight buffer layout (elements)
constexpr long W_BASE  = 32768;             // in_w^T [512,64]
constexpr long W_UP    = 0;                 // per-layer offsets
constexpr long W_QK    = 1048576;           // q^T then k^T, [2048,1024]
constexpr long W_V     = 3145728;
constexpr long W_DN    = 4194304;
constexpr long W_LAYER = 4718592;
constexpr long W_TOTAL = W_BASE + 2 * W_LAYER;   // 9,469,952
constexpr int GWT_L = 2 * NHc * 3 * Ic;     // per-layer gate-weight^T floats (49152)
}

// ---------------- scratch (device globals; no allocations allowed) ----------------
__device__ float g_h   [TOK * Dc];
__device__ float g_up  [TOK * 2 * Ic];
__device__ float g_conv[TOK * Ic];
__device__ float g_qk  [TOK * 2 * Ic];    // q cols [0,1024), k cols [1024,2048)
__device__ float g_v   [TOK * Ic];
__device__ float g_ig  [Bc * NHc * Sc];
__device__ float g_fg  [Bc * NHc * Sc];
__device__ float g_cs  [Bc * NHc * Sc];
__device__ float g_gg  [Bc * NHc * Sc];   // g_t = ig_t - cs_t
__device__ float g_M   [Bc * NHc * Sc];   // prefix max of g
__device__ __align__(16) float g_gwt[Lc * GWT_L];   // transposed gate weights
__device__ __align__(16) __half g_ah [TOK * Ic];    // activation fp16 (generic A)
__device__ __align__(16) __half g_xmh[TOK * Ic];    // x_m fp16 (v-GEMM A)
__device__ __align__(16) __half g_whi[W_TOTAL];
__device__ __align__(16) __half g_wlo[W_TOTAL];

// ---------------- helpers ----------------
__device__ __forceinline__ float warpSum(float v) {
#pragma unroll
    for (int o = 16; o > 0; o >>= 1) v += __shfl_xor_sync(0xffffffffu, v, o);
    return v;
}
__device__ __forceinline__ float warpMax(float v) {
#pragma unroll
    for (int o = 16; o > 0; o >>= 1) v = fmaxf(v, __shfl_xor_sync(0xffffffffu, v, o));
    return v;
}
__device__ __forceinline__ uint32_t smem_u32(const void* p) {
    uint32_t a;
    asm("{ .reg .u64 t; cvta.to.shared.u64 t, %1; cvt.u32.u64 %0, t; }" : "=r"(a) : "l"(p));
    return a;
}
__device__ __forceinline__ void cp16(uint32_t saddr, const void* gaddr) {
    asm volatile("cp.async.cg.shared.global [%0], [%1], 16;" :: "r"(saddr), "l"(gaddr));
}
__device__ __forceinline__ void ldm_x4(uint32_t* r, uint32_t addr) {
    asm volatile("ldmatrix.sync.aligned.m8n8.x4.shared.b16 {%0,%1,%2,%3}, [%4];"
                 : "=r"(r[0]), "=r"(r[1]), "=r"(r[2]), "=r"(r[3]) : "r"(addr));
}
__device__ __forceinline__ void mma16816(float* d, const uint32_t* a, uint32_t b0, uint32_t b1) {
    asm volatile(
        "mma.sync.aligned.m16n8k16.row.col.f32.f16.f16.f32 "
        "{%0,%1,%2,%3}, {%4,%5,%6,%7}, {%8,%9}, {%0,%1,%2,%3};"
        : "+f"(d[0]), "+f"(d[1]), "+f"(d[2]), "+f"(d[3])
        : "r"(a[0]), "r"(a[1]), "r"(a[2]), "r"(a[3]), "r"(b0), "r"(b1));
}
__device__ __forceinline__ void wsplit(float w, __half& hi, __half& lo) {
    hi = __float2half(w);
    lo = __float2half(w - __half2float(hi));
}
__device__ __forceinline__ float siluf(float z) {
    return z / (1.f + __expf(-z));
}

// ---------------- one-shot prep: x->fp16 + weights->fp16 hi/lo + gate-w transpose ----
__global__ __launch_bounds__(1024)
void prep_kernel(const float* __restrict__ x, const float* __restrict__ in_w,
                 const float* __restrict__ up_w, const float* __restrict__ q_w,
                 const float* __restrict__ k_w, const float* __restrict__ v_w,
                 const float* __restrict__ down_w,
                 const float* __restrict__ ig_w, const float* __restrict__ fg_w,
                 __half* __restrict__ xh,
                 __half* __restrict__ whi, __half* __restrict__ wlo,
                 float* __restrict__ gwt) {
    int nb = blockIdx.x;
    int tx = threadIdx.x, ty = threadIdx.y;
    if (nb < 256) {
        int idx = nb * 1024 + ty * 32 + tx;
        xh[idx] = __float2half(x[idx]);
        return;
    }
    nb -= 256;
    if (nb >= 32 + 2 * 4608) {
        int nb2 = nb - (32 + 2 * 4608);
        int mat = nb2 / 24;
        int off = (nb2 % 24) * 1024 + ty * 32 + tx;   // 0..24575
        int l = mat >> 1, gate = mat & 1;
        const float* src = (gate ? fg_w : ig_w) + (long)l * 3 * Ic * NHc;
        float val = src[off];
        int i = off >> 3, hh = off & 7;
        gwt[(long)l * GWT_L + (gate * NHc + hh) * (3 * Ic) + i] = val;
        return;
    }
    const float* W; int K, N; long dst;
    if (nb < 32) { W = in_w; K = Fc; N = Dc; dst = 0; }
    else {
        nb -= 32;
        int l = nb / 4608, r = nb % 4608;
        long lb = W_BASE + (long)l * W_LAYER;
        if (r < 1024)      { W = up_w  + (long)l * Dc * 2 * Ic; K = Dc; N = 2 * Ic; dst = lb + W_UP; nb = r; }
        else if (r < 2048) { W = q_w   + (long)l * Ic * Ic;     K = Ic; N = Ic;     dst = lb + W_QK; nb = r - 1024; }
        else if (r < 3072) { W = k_w   + (long)l * Ic * Ic;     K = Ic; N = Ic;     dst = lb + W_QK + (long)Ic * Ic; nb = r - 2048; }
        else if (r < 4096) { W = v_w   + (long)l * Ic * Ic;     K = Ic; N = Ic;     dst = lb + W_V;  nb = r - 3072; }
        else               { W = down_w+ (long)l * Ic * Dc;     K = Ic; N = Dc;     dst = lb + W_DN; nb = r - 4096; }
    }
    int ntn = N / 32;
    int n0 = (nb % ntn) * 32, k0 = (nb / ntn) * 32;
    __shared__ float sh[32][33];
    sh[ty][tx] = W[(long)(k0 + ty) * N + n0 + tx];
    __syncthreads();
    float w = sh[tx][ty];                 // = W[k0+tx][n0+ty]
    long o = dst + (long)(n0 + ty) * K + k0 + tx;
    wsplit(w, whi[o], wlo[o]);
}

// ---------------- GEMM core (128x64, BK=32, 3-stage), fp16 2-term ----------------
template<bool ACC, bool BIAS, bool SPLIT>
__device__ __forceinline__
void gemm_body(const __half* __restrict__ A,
               const __half* __restrict__ Bhi, const __half* __restrict__ Blo,
               const float* __restrict__ bias, float* __restrict__ C, int N, int Kd,
               __half* __restrict__ Sh, int splitN,
               int bm, int bn, char* sm) {
    uint32_t sbase = smem_u32(sm);
    int tid = threadIdx.x, wid = tid >> 5, lane = tid & 31;
    int m0 = (wid >> 1) * 32, n0 = (wid & 1) * 32;

    float acc[2][4][4];
#pragma unroll
    for (int i = 0; i < 2; i++)
#pragma unroll
        for (int j = 0; j < 4; j++)
#pragma unroll
            for (int t = 0; t < 4; t++) acc[i][j][t] = 0.f;

    const int nchunk = Kd >> 5;

    auto load_chunk = [&](int stage, int k0) {
        uint32_t sA = sbase + stage * G_STG;
#pragma unroll
        for (int u2 = 0; u2 < 2; u2++) {
            int u = u2 * 256 + tid;             // 0..511: A 128 rows x 4 chunks
            int row = u >> 2;
            uint32_t off = (uint32_t)u << 4;
            uint32_t sw = off ^ ((off >> 3) & 0x30);
            long ga = (long)(bm + row) * Kd + k0 + ((u & 3) << 3);
            cp16(sA + sw, A + ga);
        }
        {
            int u = tid;                        // B: 64 rows x 4 chunks = 256
            int row = u >> 2;
            uint32_t off = (uint32_t)u << 4;
            uint32_t sw = off ^ ((off >> 3) & 0x30);
            long gb = (long)(bn + row) * Kd + k0 + ((u & 3) << 3);
            cp16(sA + G_TILE_A + sw,            Bhi + gb);
            cp16(sA + G_TILE_A + G_TILE_B + sw, Blo + gb);
        }
        asm volatile("cp.async.commit_group;" ::: "memory");
    };

    // precomputed LDSM offsets (k16=0); k16=1 = XOR 32
    int rsel = lane & 15;
    uint32_t csel = ((uint32_t)(lane >> 4) & 1) << 4;
    uint32_t offA[2], offB[2];
#pragma unroll
    for (int i = 0; i < 2; i++) {
        uint32_t r = (uint32_t)(m0 + i * 16 + rsel);
        offA[i] = r * 64 + (csel ^ ((r * 8) & 0x30));
    }
#pragma unroll
    for (int p = 0; p < 2; p++) {
        uint32_t r = (uint32_t)(n0 + p * 16 + rsel);
        offB[p] = r * 64 + (csel ^ ((r * 8) & 0x30));
    }

    load_chunk(0, 0);
    if (nchunk > 1) load_chunk(1, 32);
    else asm volatile("cp.async.commit_group;" ::: "memory");

    for (int c = 0; c < nchunk; c++) {
        asm volatile("cp.async.wait_group 1;" ::: "memory");
        __syncthreads();
        if (c + 2 < nchunk) load_chunk((c + 2) % 3, (c + 2) << 5);
        else asm volatile("cp.async.commit_group;" ::: "memory");

        uint32_t base = sbase + (c % 3) * G_STG;
#pragma unroll
        for (int k16 = 0; k16 < 2; k16++) {
            uint32_t x = (uint32_t)k16 * 32;
            uint32_t ah[2][4], bh[2][4], bl[2][4];
#pragma unroll
            for (int i = 0; i < 2; i++) ldm_x4(ah[i], base + (offA[i] ^ x));
#pragma unroll
            for (int p = 0; p < 2; p++) {
                ldm_x4(bh[p], base + G_TILE_A + (offB[p] ^ x));
                ldm_x4(bl[p], base + G_TILE_A + G_TILE_B + (offB[p] ^ x));
            }
            // term-major: T1 = A*Whi, T2 = A*Wlo
#pragma unroll
            for (int i = 0; i < 2; i++)
#pragma unroll
                for (int p = 0; p < 2; p++)
#pragma unroll
                    for (int q = 0; q < 2; q++)
                        mma16816(acc[i][p * 2 + q], ah[i], bh[p][q], bh[p][q + 2]);
#pragma unroll
            for (int i = 0; i < 2; i++)
#pragma unroll
                for (int p = 0; p < 2; p++)
#pragma unroll
                    for (int q = 0; q < 2; q++)
                        mma16816(acc[i][p * 2 + q], ah[i], bl[p][q], bl[p][q + 2]);
        }
    }

    int gid = lane >> 2, tig = lane & 3;
#pragma unroll
    for (int i = 0; i < 2; i++) {
        int row0 = bm + m0 + i * 16 + gid;
#pragma unroll
        for (int j = 0; j < 4; j++) {
            int col = bn + n0 + j * 8 + tig * 2;
            float o0 = acc[i][j][0], o1 = acc[i][j][1];
            float o2 = acc[i][j][2], o3 = acc[i][j][3];
            if (BIAS) {
                float b0 = bias[col], b1 = bias[col + 1];
                o0 += b0; o1 += b1; o2 += b0; o3 += b1;
            }
            float* p0 = C + (long)row0 * N + col;
            float* p1 = C + (long)(row0 + 8) * N + col;
            if (ACC) {
                float2 c0 = *(float2*)p0, c1 = *(float2*)p1;
                o0 += c0.x; o1 += c0.y; o2 += c1.x; o3 += c1.y;
            }
            *(float2*)p0 = make_float2(o0, o1);
            *(float2*)p1 = make_float2(o2, o3);
            if (SPLIT && col < splitN) {
                *(__half2*)(Sh + (long)row0 * splitN + col) =
                    __floats2half2_rn(o0, o1);
                *(__half2*)(Sh + (long)(row0 + 8) * splitN + col) =
                    __floats2half2_rn(o2, o3);
            }
        }
    }
}

template<bool ACC, bool BIAS, bool SPLIT>
__global__ __launch_bounds__(256, 3)
void mma_gemm(const __half* __restrict__ A,
              const __half* __restrict__ Bhi, const __half* __restrict__ Blo,
              const float* __restrict__ bias, float* __restrict__ C, int N, int Kd,
              __half* __restrict__ Sh, int splitN) {
    extern __shared__ char dsm[];
    char* sm = (char*)(((uintptr_t)dsm + 1023) & ~(uintptr_t)1023);
    gemm_body<ACC, BIAS, SPLIT>(A, Bhi, Blo, bias, C, N, Kd, Sh, splitN,
                                blockIdx.y * 128, blockIdx.x * 64, sm);
}

// merged dual-operand GEMM: blockIdx.x < nx1 -> op1, else op2 (same M, same Kd)
__global__ __launch_bounds__(256, 3)
void mma_gemm2(const __half* __restrict__ A1,
               const __half* __restrict__ B1h, const __half* __restrict__ B1l,
               float* __restrict__ C1, int N1, int nx1,
               const __half* __restrict__ A2,
               const __half* __restrict__ B2h, const __half* __restrict__ B2l,
               float* __restrict__ C2, int N2, int Kd) {
    extern __shared__ char dsm[];
    char* sm = (char*)(((uintptr_t)dsm + 1023) & ~(uintptr_t)1023);
    int bx = blockIdx.x;
    if (bx < nx1) {
        gemm_body<false, false, false>(A1, B1h, B1l, nullptr, C1, N1, Kd,
                                       nullptr, 0, blockIdx.y * 128, bx * 64, sm);
    } else {
        gemm_body<false, false, false>(A2, B2h, B2l, nullptr, C2, N2, Kd,
                                       nullptr, 0, blockIdx.y * 128, (bx - nx1) * 64, sm);
    }
}

// ---------------- LayerNorm over D=512 -> fp16 directly ----------------
__global__ __launch_bounds__(256)
void layernorm_kernel(const float* __restrict__ in, const float* __restrict__ w,
                      const float* __restrict__ b, __half* __restrict__ oh) {
    int row = blockIdx.x;
    const float* x = in + row * Dc;
    int tid = threadIdx.x;
    float v0 = x[tid], v1 = x[tid + 256];
    float s = v0 + v1, sq = v0 * v0 + v1 * v1;
    s = warpSum(s); sq = warpSum(sq);
    __shared__ float sS[8], sQ[8];
    int w8 = tid >> 5, lane = tid & 31;
    if (lane == 0) { sS[w8] = s; sQ[w8] = sq; }
    __syncthreads();
    float Sv = 0.f, Qv = 0.f;
#pragma unroll
    for (int i = 0; i < 8; i++) { Sv += sS[i]; Qv += sQ[i]; }
    float mu = Sv * (1.f / Dc);
    float var = Qv * (1.f / Dc) - mu * mu;
    float r = rsqrtf(var + 1e-5f);
    float y0 = (v0 - mu) * r * w[tid]       + b[tid];
    float y1 = (v1 - mu) * r * w[tid + 256] + b[tid + 256];
    oh[row * Dc + tid]       = __float2half(y0);
    oh[row * Dc + tid + 256] = __float2half(y1);
}

// ---------------- causal conv (K=4) + SiLU -> fp32 + fp16 ----------------
__global__ __launch_bounds__(256)
void conv_silu_kernel(const float* __restrict__ up, const float* __restrict__ cw,
                      const float* __restrict__ cb, float* __restrict__ out,
                      __half* __restrict__ oh) {
    int idx = blockIdx.x * 256 + threadIdx.x;   // over TOK*I
    int i = idx & (Ic - 1);
    int bs = idx >> 10;
    int s = bs & (Sc - 1);
    float acc = cb[i];
#pragma unroll
    for (int j = 0; j < Kc; j++) {
        int sp = s - (Kc - 1) + j;
        if (sp >= 0) acc += up[(bs - (Kc - 1) + j) * (2 * Ic) + i] * cw[i * Kc + j];
    }
    float sg = 1.f / (1.f + __expf(-acc));
    float o = acc * sg;
    out[idx] = o;
    oh[idx] = __float2half(o);
}

// ---------------- gates v2: 4 tokens per block, weight reuse x4 ----------------
__global__ __launch_bounds__(512)
void gates_kernel(const float* __restrict__ qk, const float* __restrict__ v,
                  const float* __restrict__ gwt,
                  const float* __restrict__ igb, const float* __restrict__ fgb,
                  float* __restrict__ ig, float* __restrict__ fg) {
    extern __shared__ float rows[];            // [4][3072]
    int bs0 = blockIdx.x * 4;
    for (int u = threadIdx.x; u < 4 * 3 * Ic; u += 512) {
        int gg2 = u / (3 * Ic);
        int i = u - gg2 * 3 * Ic;
        long bs = bs0 + gg2;
        float val;
        if (i < Ic)           val = qk[bs * 2048 + i];
        else if (i < 2 * Ic)  val = qk[bs * 2048 + 1024 + (i - Ic)];
        else                  val = v[bs * Ic + (i - 2 * Ic)];
        rows[gg2 * 3 * Ic + i] = val;
    }
    __syncthreads();
    int w = threadIdx.x >> 5, lane = threadIdx.x & 31;
    int h = w & 7, gate = w >> 3;
    const float* W = gwt + (gate * NHc + h) * (3 * Ic);
    float sum[4] = {0.f, 0.f, 0.f, 0.f};
    for (int i = lane * 4; i < 3 * Ic; i += 128) {
        float4 wv = *(const float4*)(W + i);
#pragma unroll
        for (int gg2 = 0; gg2 < 4; gg2++) {
            float4 rv = *(const float4*)(rows + gg2 * 3 * Ic + i);
            sum[gg2] += rv.x * wv.x + rv.y * wv.y + rv.z * wv.z + rv.w * wv.w;
        }
    }
#pragma unroll
    for (int gg2 = 0; gg2 < 4; gg2++) sum[gg2] = warpSum(sum[gg2]);
    if (lane == 0) {
#pragma unroll
        for (int gg2 = 0; gg2 < 4; gg2++) {
            int bs = bs0 + gg2;
            int b = bs >> 9, s = bs & (Sc - 1);
            int idx = (b * NHc + h) * Sc + s;
            if (gate == 0) ig[idx] = sum[gg2] + igb[h];
            else           fg[idx] = sum[gg2] + fgb[h];
        }
    }
}

// ---------------- scan: cs = cumsum(logsigmoid(fg)); g = ig - cs; M = prefixmax(g) --
__global__ __launch_bounds__(32)
void scan_kernel(const float* __restrict__ fg, const float* __restrict__ ig,
                 float* __restrict__ cs, float* __restrict__ g, float* __restrict__ M) {
    int bh = blockIdx.x, lane = threadIdx.x;
    const float* fp = fg + bh * Sc;
    const float* ip = ig + bh * Sc;
    int base = lane * 16;

    float lcs[16];
    float run = 0.f;
#pragma unroll
    for (int i = 0; i < 16; i++) {
        float f = fp[base + i];
        float ls = fminf(f, 0.f) - log1pf(__expf(-fabsf(f)));
        run += ls;
        lcs[i] = run;
    }
    float v = run;
#pragma unroll
    for (int o = 1; o < 32; o <<= 1) {
        float u = __shfl_up_sync(0xffffffffu, v, o);
        if (lane >= o) v += u;
    }
    float ex = v - run;

    float gv[16], pm[16];
    float rm = -1e30f;
#pragma unroll
    for (int i = 0; i < 16; i++) {
        lcs[i] += ex;
        gv[i] = ip[base + i] - lcs[i];
        rm = fmaxf(rm, gv[i]);
        pm[i] = rm;
    }
    float w = rm;
#pragma unroll
    for (int o = 1; o < 32; o <<= 1) {
        float u = __shfl_up_sync(0xffffffffu, w, o);
        if (lane >= o) w = fmaxf(w, u);
    }
    float exm = __shfl_up_sync(0xffffffffu, w, 1);
    if (lane == 0) exm = -1e30f;

#pragma unroll
    for (int i = 0; i < 16; i++) {
        cs[bh * Sc + base + i] = lcs[i];
        g [bh * Sc + base + i] = gv[i];
        M [bh * Sc + base + i] = fmaxf(exm, pm[i]);
    }
}

// ---------------- mLSTM v6: triangle-paired + FUSED groupnorm/skip/z-gate epilogue --
// grid (B*NH, 8); emits hs in fp16 directly (down-GEMM A operand).
__global__ __launch_bounds__(256)
void mlstm_kernel(const float* __restrict__ qk, const float* __restrict__ v,
                  const float* __restrict__ g, const float* __restrict__ M,
                  const float* __restrict__ cs,
                  const float* __restrict__ gnw, const float* __restrict__ skw,
                  const float* __restrict__ conv, const float* __restrict__ up,
                  __half* __restrict__ oh) {
    extern __shared__ float4 dyn4[];
    float4* ks4 = dyn4;                       // [tt*33 + c4]   (1056)
    float4* vs4 = dyn4 + 1056;                // [tt*33 + c4]   (1056)
    float4* qA  = dyn4 + 2112;                // [warp*128 + r*32 + d4] (1024)
    float4* qB  = dyn4 + 3136;                // (1024)
    float4* cst = dyn4 + 4160;                // [warp*32 + lane] (256)

    int bh = blockIdx.x;
    int b = bh >> 3, h = bh & 7;
    int warp = threadIdx.x >> 5, lane = threadIdx.x & 31;
    int y1 = blockIdx.y, y2 = 15 - y1;
    int s0A = y1 * 32 + warp * 4;
    int s0B = y2 * 32 + warp * 4;

    const float sc = 0.08838834764831845f;   // 1/sqrt(128)
    float MsA[4], csA[4], MsB[4], csB[4];
#pragma unroll
    for (int r = 0; r < 4; r++) {
        int sa = s0A + r, sb = s0B + r;
        float4 qa = *(const float4*)(qk + (long)(b * Sc + sa) * 2048 + h * DHc + lane * 4);
        qa.x *= sc; qa.y *= sc; qa.z *= sc; qa.w *= sc;
        qA[warp * 128 + r * 32 + lane] = qa;
        float4 qb = *(const float4*)(qk + (long)(b * Sc + sb) * 2048 + h * DHc + lane * 4);
        qb.x *= sc; qb.y *= sc; qb.z *= sc; qb.w *= sc;
        qB[warp * 128 + r * 32 + lane] = qb;
        MsA[r] = M[bh * Sc + sa]; csA[r] = cs[bh * Sc + sa];
        MsB[r] = M[bh * Sc + sb]; csB[r] = cs[bh * Sc + sb];
    }
    __syncwarp();

    const float* gg = g + bh * Sc;
    float oA[4][4], oB[4][4];
#pragma unroll
    for (int r = 0; r < 4; r++)
#pragma unroll
        for (int j = 0; j < 4; j++) { oA[r][j] = 0.f; oB[r][j] = 0.f; }
    float accA[4] = {0.f, 0.f, 0.f, 0.f};
    float accB[4] = {0.f, 0.f, 0.f, 0.f};

    int ntile = y2 + 1;
    for (int tt0 = 0; tt0 < ntile; tt0++) {
        int t0 = tt0 * 32;
        __syncthreads();
        for (int idx = threadIdx.x; idx < 32 * 32; idx += 256) {
            int tt = idx >> 5, c4 = idx & 31;
            long tr = (long)(b * Sc + t0 + tt);
            ks4[tt * 33 + c4] = *(const float4*)(qk + tr * 2048 + 1024 + h * DHc + c4 * 4);
            vs4[tt * 33 + c4] = *(const float4*)(v + tr * 1024 + h * DHc + c4 * 4);
        }
        __syncthreads();

        bool actA = (tt0 <= y1);
        int t = t0 + lane;
        float gv = gg[t];

        float T0B = warpMax((t <= s0B + 3) ? gv : -1e30f);
        float wtB = (t <= s0B + 3) ? __expf(gv - T0B) : 0.f;
        float T0A = 0.f, wtA = 0.f;
        if (actA) {
            T0A = warpMax((t <= s0A + 3) ? gv : -1e30f);
            wtA = (t <= s0A + 3) ? __expf(gv - T0A) : 0.f;
        }

        float dA[4] = {0.f, 0.f, 0.f, 0.f};
        float dB[4] = {0.f, 0.f, 0.f, 0.f};
        if (actA) {
#pragma unroll
            for (int d4 = 0; d4 < 32; d4++) {
                float4 k4 = ks4[lane * 33 + d4];
#pragma unroll
                for (int r = 0; r < 4; r++) {
                    float4 qa = qA[warp * 128 + r * 32 + d4];
                    dA[r] += qa.x * k4.x + qa.y * k4.y + qa.z * k4.z + qa.w * k4.w;
                    float4 qb = qB[warp * 128 + r * 32 + d4];
                    dB[r] += qb.x * k4.x + qb.y * k4.y + qb.z * k4.z + qb.w * k4.w;
                }
            }
        } else {
#pragma unroll
            for (int d4 = 0; d4 < 32; d4++) {
                float4 k4 = ks4[lane * 33 + d4];
#pragma unroll
                for (int r = 0; r < 4; r++) {
                    float4 qb = qB[warp * 128 + r * 32 + d4];
                    dB[r] += qb.x * k4.x + qb.y * k4.y + qb.z * k4.z + qb.w * k4.w;
                }
            }
        }

        if (actA) {
            float cA[4];
#pragma unroll
            for (int r = 0; r < 4; r++) {
                float wf = wtA * __expf(T0A - MsA[r]);
                cA[r] = (t <= s0A + r) ? dA[r] * wf : 0.f;
                accA[r] += cA[r];
            }
            cst[warp * 32 + lane] = make_float4(cA[0], cA[1], cA[2], cA[3]);
            __syncwarp();
#pragma unroll
            for (int tt = 0; tt < 32; tt++) {
                float4 c4v = cst[warp * 32 + tt];
                float4 v4 = vs4[tt * 33 + lane];
                oA[0][0] += c4v.x * v4.x; oA[0][1] += c4v.x * v4.y; oA[0][2] += c4v.x * v4.z; oA[0][3] += c4v.x * v4.w;
                oA[1][0] += c4v.y * v4.x; oA[1][1] += c4v.y * v4.y; oA[1][2] += c4v.y * v4.z; oA[1][3] += c4v.y * v4.w;
                oA[2][0] += c4v.z * v4.x; oA[2][1] += c4v.z * v4.y; oA[2][2] += c4v.z * v4.z; oA[2][3] += c4v.z * v4.w;
                oA[3][0] += c4v.w * v4.x; oA[3][1] += c4v.w * v4.y; oA[3][2] += c4v.w * v4.z; oA[3][3] += c4v.w * v4.w;
            }
            __syncwarp();
        }
        {
            float cB[4];
#pragma unroll
            for (int r = 0; r < 4; r++) {
                float wf = wtB * __expf(T0B - MsB[r]);
                cB[r] = (t <= s0B + r) ? dB[r] * wf : 0.f;
                accB[r] += cB[r];
            }
            cst[warp * 32 + lane] = make_float4(cB[0], cB[1], cB[2], cB[3]);
            __syncwarp();
#pragma unroll
            for (int tt = 0; tt < 32; tt++) {
                float4 c4v = cst[warp * 32 + tt];
                float4 v4 = vs4[tt * 33 + lane];
                oB[0][0] += c4v.x * v4.x; oB[0][1] += c4v.x * v4.y; oB[0][2] += c4v.x * v4.z; oB[0][3] += c4v.x * v4.w;
                oB[1][0] += c4v.y * v4.x; oB[1][1] += c4v.y * v4.y; oB[1][2] += c4v.y * v4.z; oB[1][3] += c4v.y * v4.w;
                oB[2][0] += c4v.z * v4.x; oB[2][1] += c4v.z * v4.y; oB[2][2] += c4v.z * v4.z; oB[2][3] += c4v.z * v4.w;
                oB[3][0] += c4v.w * v4.x; oB[3][1] += c4v.w * v4.y; oB[3][2] += c4v.w * v4.z; oB[3][3] += c4v.w * v4.w;
            }
            __syncwarp();
        }
    }

    // ---- fused epilogue: normalize + groupnorm + skip + z-gate -> fp16 hs ----
    float4 gw = *(const float4*)(gnw + h * DHc + lane * 4);
    float4 sw = *(const float4*)(skw + h * DHc + lane * 4);
#pragma unroll
    for (int side = 0; side < 2; side++) {
        float* accS  = side ? accB : accA;
        float (*oS)[4] = side ? oB : oA;
        float* MsS   = side ? MsB : MsA;
        float* csS   = side ? csB : csA;
        int s0 = side ? s0B : s0A;
#pragma unroll
        for (int r = 0; r < 4; r++) {
            float a = warpSum(accS[r]);
            float nrm = fmaxf(fabsf(a), __expf(-(csS[r] + MsS[r])));
            float inv = 1.f / (nrm + 1e-6f);
            float x0 = oS[r][0] * inv, x1 = oS[r][1] * inv;
            float x2 = oS[r][2] * inv, x3 = oS[r][3] * inv;
            float sm1 = warpSum(x0 + x1 + x2 + x3);
            float sm2 = warpSum(x0 * x0 + x1 * x1 + x2 * x2 + x3 * x3);
            float mu = sm1 * (1.f / DHc);
            float var = sm2 * (1.f / DHc) - mu * mu;
            float rr = rsqrtf(var + 1e-5f);
            long bs = (long)(b * Sc + s0 + r);
            long ci = bs * Ic + h * DHc + lane * 4;
            float4 cv = *(const float4*)(conv + ci);
            float4 z4 = *(const float4*)(up + bs * 2048 + 1024 + h * DHc + lane * 4);
            float r0 = ((x0 - mu) * rr * gw.x + sw.x * cv.x) * siluf(z4.x);
            float r1 = ((x1 - mu) * rr * gw.y + sw.y * cv.y) * siluf(z4.y);
            float r2 = ((x2 - mu) * rr * gw.z + sw.z * cv.z) * siluf(z4.z);
            float r3 = ((x3 - mu) * rr * gw.w + sw.w * cv.w) * siluf(z4.w);
            __half2* dst = (__half2*)(oh + ci);
            dst[0] = __floats2half2_rn(r0, r1);
            dst[1] = __floats2half2_rn(r2, r3);
        }
    }
}

// ---------------- tail ----------------
__global__ __launch_bounds__(256)
void final_kernel(const float* __restrict__ h, const float* __restrict__ pw,
                  const float* __restrict__ pb, const float* __restrict__ w1,
                  const float* __restrict__ b1, const float* __restrict__ w2,
                  const float* __restrict__ b2, float* __restrict__ out) {
    int b = blockIdx.x;
    __shared__ float ln[Dc];
    __shared__ float hid[H1c];
    __shared__ float sS[8], sQ[8];
    const float* x = h + (b * Sc + Sc - 1) * Dc;
    int tid = threadIdx.x;
    float v0 = x[tid], v1 = x[tid + 256];
    float s = v0 + v1, sq = v0 * v0 + v1 * v1;
    s = warpSum(s); sq = warpSum(sq);
    int w = tid >> 5, lane = tid & 31;
    if (lane == 0) { sS[w] = s; sQ[w] = sq; }
    __syncthreads();
    float Sv = 0.f, Qv = 0.f;
#pragma unroll
    for (int i = 0; i < 8; i++) { Sv += sS[i]; Qv += sQ[i]; }
    float mu = Sv * (1.f / Dc);
    float var = Qv * (1.f / Dc) - mu * mu;
    float r = rsqrtf(var + 1e-5f);
    ln[tid]       = (v0 - mu) * r * pw[tid]       + pb[tid];
    ln[tid + 256] = (v1 - mu) * r * pw[tid + 256] + pb[tid + 256];
    __syncthreads();
#pragma unroll
    for (int jj = 0; jj < 4; jj++) {
        int o = w + 8 * jj;
        float sum = 0.f;
        for (int d = lane; d < Dc; d += 32) sum += ln[d] * w1[d * H1c + o];
        sum = warpSum(sum);
        if (lane == 0) hid[o] = fmaxf(sum + b1[o], 0.f);
    }
    __syncthreads();
    if (tid < OUTc) {
        float s2 = b2[tid];
#pragma unroll
        for (int j = 0; j < H1c; j++) s2 += hid[j] * w2[j * OUTc + tid];
        out[b * OUTc + tid] = s2;
    }
}

// ---------------- launch ----------------
extern "C" void kernel_launch(void* const* d_in, const int* in_sizes, int n_in,
                              void* d_out, int out_size) {
    const float* x     = (const float*)d_in[0];
    const float* in_w  = (const float*)d_in[1];
    const float* in_b  = (const float*)d_in[2];
    const float* ln_w  = (const float*)d_in[3];
    const float* ln_b  = (const float*)d_in[4];
    const float* up_w  = (const float*)d_in[5];
    const float* conv_w= (const float*)d_in[6];
    const float* conv_b= (const float*)d_in[7];
    const float* q_w   = (const float*)d_in[8];
    const float* k_w   = (const float*)d_in[9];
    const float* v_w   = (const float*)d_in[10];
    const float* ig_w  = (const float*)d_in[11];
    const float* ig_b  = (const float*)d_in[12];
    const float* fg_w  = (const float*)d_in[13];
    const float* fg_b  = (const float*)d_in[14];
    const float* gn_w  = (const float*)d_in[15];
    const float* skip_w= (const float*)d_in[16];
    const float* down_w= (const float*)d_in[17];
    const float* post_w= (const float*)d_in[18];
    const float* post_b= (const float*)d_in[19];
    const float* h1_w  = (const float*)d_in[20];
    const float* h1_b  = (const float*)d_in[21];
    const float* h2_w  = (const float*)d_in[22];
    const float* h2_b  = (const float*)d_in[23];

    float *h, *up, *conv, *qkb, *v, *ig, *fg, *cs, *gg, *Mg, *gwt;
    __half *ah, *xmh, *whi, *wlo;
    cudaGetSymbolAddress((void**)&h,    g_h);
    cudaGetSymbolAddress((void**)&up,   g_up);
    cudaGetSymbolAddress((void**)&conv, g_conv);
    cudaGetSymbolAddress((void**)&qkb,  g_qk);
    cudaGetSymbolAddress((void**)&v,    g_v);
    cudaGetSymbolAddress((void**)&ig,   g_ig);
    cudaGetSymbolAddress((void**)&fg,   g_fg);
    cudaGetSymbolAddress((void**)&cs,   g_cs);
    cudaGetSymbolAddress((void**)&gg,   g_gg);
    cudaGetSymbolAddress((void**)&Mg,   g_M);
    cudaGetSymbolAddress((void**)&gwt,  g_gwt);
    cudaGetSymbolAddress((void**)&ah,   g_ah);
    cudaGetSymbolAddress((void**)&xmh,  g_xmh);
    cudaGetSymbolAddress((void**)&whi,  g_whi);
    cudaGetSymbolAddress((void**)&wlo,  g_wlo);

    cudaFuncSetAttribute(mma_gemm<false, false, false>, cudaFuncAttributeMaxDynamicSharedMemorySize, DSMG);
    cudaFuncSetAttribute(mma_gemm<false, false, true >, cudaFuncAttributeMaxDynamicSharedMemorySize, DSMG);
    cudaFuncSetAttribute(mma_gemm<false, true,  false>, cudaFuncAttributeMaxDynamicSharedMemorySize, DSMG);
    cudaFuncSetAttribute(mma_gemm<true,  false, false>, cudaFuncAttributeMaxDynamicSharedMemorySize, DSMG);
    cudaFuncSetAttribute(mma_gemm2, cudaFuncAttributeMaxDynamicSharedMemorySize, DSMG);
    cudaFuncSetAttribute(mlstm_kernel, cudaFuncAttributeMaxDynamicSharedMemorySize, MSMEM);
    cudaFuncSetAttribute(gates_kernel, cudaFuncAttributeMaxDynamicSharedMemorySize, GSMEM);

    // launch 0: all weight conversion + x convert + gate-w transpose (one kernel)
    prep_kernel<<<256 + 32 + 2 * 4608 + 96, dim3(32, 32)>>>(
        x, in_w, up_w, q_w, k_w, v_w, down_w, ig_w, fg_w, ah, whi, wlo, gwt);
    // launch 1: h = x @ in_w + in_b
    mma_gemm<false, true, false><<<dim3(Dc / 64, TOK / 128), 256, DSMG>>>(
        ah, whi, wlo, in_b, h, Dc, Fc, nullptr, 0);

    for (int l = 0; l < Lc; l++) {
        long lb = W_BASE + (long)l * W_LAYER;
        layernorm_kernel<<<TOK, 256>>>(h, ln_w + l * Dc, ln_b + l * Dc, ah);
        // up = xn @ up_w[l]  (+ x_m fp16 for v-GEMM)   << PROFILED SLOT >>
        mma_gemm<false, false, true><<<dim3(2 * Ic / 64, TOK / 128), 256, DSMG>>>(
            ah, whi + lb + W_UP, wlo + lb + W_UP, nullptr, up, 2 * Ic, Dc, xmh, Ic);
        // conv_act = silu(causal_conv(x_m))  (+ its own fp16)
        conv_silu_kernel<<<TOK * Ic / 256, 256>>>(up, conv_w + l * Ic * Kc, conv_b + l * Ic,
                                                  conv, ah);
        // merged launch: qk = conv @ [q|k]  AND  v = x_m @ v_w  (K=1024 both)
        mma_gemm2<<<dim3(2 * Ic / 64 + Ic / 64, TOK / 128), 256, DSMG>>>(
            ah, whi + lb + W_QK, wlo + lb + W_QK, qkb, 2 * Ic, 2 * Ic / 64,
            xmh, whi + lb + W_V, wlo + lb + W_V, v, Ic, Ic);
        // gates (4-token blocked, 4 CTAs/SM) + scan
        gates_kernel<<<TOK / 4, 512, GSMEM>>>(qkb, v, gwt + (long)l * GWT_L,
                                              ig_b + l * NHc, fg_b + l * NHc, ig, fg);
        scan_kernel<<<Bc * NHc, 32>>>(fg, ig, cs, gg, Mg);
        // attention + fused groupnorm/skip/z-gate -> hs fp16 (down-GEMM A)
        mlstm_kernel<<<dim3(Bc * NHc, 8), 256, MSMEM>>>(
            qkb, v, gg, Mg, cs, gn_w + l * Ic, skip_w + l * Ic, conv, up, ah);
        // h += hs @ down_w[l]
        mma_gemm<true, false, false><<<dim3(Dc / 64, TOK / 128), 256, DSMG>>>(
            ah, whi + lb + W_DN, wlo + lb + W_DN, nullptr, h, Dc, Ic, nullptr, 0);
    }

    final_kernel<<<Bc, 256>>>(h, post_w, post_b, h1_w, h1_b, h2_w, h2_b, (float*)d_out);
}